// round 4
// baseline (speedup 1.0000x reference)
#include <cuda_runtime.h>

#define F_IN 512
#define HID  64
#define NCLS 16
#define NMAX 100000
#define EMAX 3200000

typedef unsigned long long ull;

// ---------------- scratch (static device globals; no allocation) -------------
__device__ __align__(16) float g_h1[NMAX * HID];    // x @ W1^T
__device__ __align__(16) float g_r1[NMAX * HID];    // relu(agg1 + b1)
__device__ __align__(16) float g_h2[NMAX * NCLS];   // r1 @ W2^T
__device__ __align__(16) float g_W1p[F_IN * HID];   // W1 k-pair-interleaved:
                                                    // [k/2][n][parity]
__device__ float g_deg[NMAX];                       // deg -> dinv in place
__device__ int   g_off[NMAX + 1];                   // CSR offsets (by target)
__device__ int   g_cur[NMAX];                       // counts -> cursors
__device__ int2  g_edge[EMAX];                      // packed (src, norm)

// ---------------- PTX helpers -------------------------------------------------
__device__ __forceinline__ unsigned smem_u32(const void* p) {
    unsigned r;
    asm("{ .reg .u64 u; cvta.to.shared.u64 u, %1; cvt.u32.u64 %0, u; }"
        : "=r"(r) : "l"(p));
    return r;
}
__device__ __forceinline__ void cp16(unsigned d, const void* s) {
    asm volatile("cp.async.cg.shared.global [%0], [%1], 16;" :: "r"(d), "l"(s));
}
__device__ __forceinline__ ull fma2(ull a, ull b, ull c) {
    ull d; asm("fma.rn.f32x2 %0, %1, %2, %3;" : "=l"(d) : "l"(a), "l"(b), "l"(c));
    return d;
}
__device__ __forceinline__ void unpack2(ull v, float& lo, float& hi) {
    asm("mov.b64 {%0, %1}, %2;" : "=f"(lo), "=f"(hi) : "l"(v));
}

// ---------------- CSR build ---------------------------------------------------
__global__ void k_init(int N) {
    int i = blockIdx.x * blockDim.x + threadIdx.x;
    if (i < N) { g_cur[i] = 0; g_deg[i] = 1.0f; }  // self-loop weight
}
__global__ void k_count(const int* __restrict__ col, const float* __restrict__ ew, int E) {
    int i = blockIdx.x * blockDim.x + threadIdx.x;
    if (i < E) {
        int c = col[i];
        atomicAdd(&g_cur[c], 1);
        atomicAdd(&g_deg[c], ew[i]);
    }
}
__global__ void k_dinv(int N) {
    int i = blockIdx.x * blockDim.x + threadIdx.x;
    if (i < N) {
        float d = g_deg[i];
        g_deg[i] = (d > 0.0f) ? rsqrtf(d) : 0.0f;
    }
}
// single-block exclusive scan of g_cur -> g_off (and reset g_cur = g_off)
__global__ void __launch_bounds__(1024) k_scan(int N) {
    __shared__ int sh[1024];
    int t = threadIdx.x;
    int chunk = (N + 1023) >> 10;
    int beg = t * chunk;
    int end = beg + chunk; if (end > N) end = N; if (beg > N) beg = N;
    int s = 0;
    for (int i = beg; i < end; i++) s += g_cur[i];
    sh[t] = s;
    __syncthreads();
    for (int off = 1; off < 1024; off <<= 1) {
        int v = (t >= off) ? sh[t - off] : 0;
        __syncthreads();
        sh[t] += v;
        __syncthreads();
    }
    int run = sh[t] - s;  // exclusive base for this chunk
    for (int i = beg; i < end; i++) {
        int c = g_cur[i];
        g_off[i] = run;
        g_cur[i] = run;
        run += c;
    }
    if (t == 0) g_off[N] = sh[1023];
}
__global__ void k_scatter(const int* __restrict__ row, const int* __restrict__ col,
                          const float* __restrict__ ew, int E) {
    int i = blockIdx.x * blockDim.x + threadIdx.x;
    if (i >= E) return;
    int r = row[i], c = col[i];
    float nrm = g_deg[r] * ew[i] * g_deg[c];  // g_deg holds dinv here
    int p = atomicAdd(&g_cur[c], 1);
    int2 v; v.x = r; v.y = __float_as_int(nrm);
    g_edge[p] = v;
}

// ---------------- W1 re-interleave: g_W1p[k/2][n][k&1] = W1[n][k] -------------
__global__ void k_w1p(const float* __restrict__ W1) {
    int i = blockIdx.x * blockDim.x + threadIdx.x;
    if (i < HID * F_IN) {
        int n = i >> 9, k = i & 511;
        g_W1p[(k >> 1) * (2 * HID) + n * 2 + (k & 1)] = W1[i];
    }
}

// ---------------- GEMM1: h1[N,64] = x[N,512] @ W1[64,512]^T ------------------
// f32x2 lanes split along K (even/odd partial sums), so BOTH operand pairs are
// natural 8B loads: A from [m][k] smem (cp.async, no transpose), B from the
// pair-interleaved g_W1p. Zero register-duplication MOVs in the inner loop.
// BM=64, BN=64, BK=32; 256 threads; 4m x 4n per thread; double-buffered.
#define G1_BK   32
#define G1_NT   (F_IN / G1_BK)          // 16 tiles
#define G1_ASTR 36                      // A row stride in floats (32 + 4 pad)

__global__ void __launch_bounds__(256, 2) k_gemm1(const float* __restrict__ x, int N) {
    __shared__ float As[2][64 * G1_ASTR];        // [m][k] padded
    __shared__ float Bs[2][(G1_BK / 2) * 2 * HID];  // [kp][n*2+parity]

    int tid = threadIdx.x;
    int tx = tid & 15;        // n0 = 4*tx
    int ty = tid >> 4;        // m0 = 4*ty
    int n0 = tx * 4;
    int m0 = ty * 4;
    int bm = blockIdx.x * 64;

    ull acc[4][4];            // [m][n] -> (even-k sum, odd-k sum)
#pragma unroll
    for (int i = 0; i < 4; i++)
#pragma unroll
        for (int j = 0; j < 4; j++) acc[i][j] = 0ull;

    auto stage = [&](int t, int s) {
        int k0 = t * G1_BK;
        // A: 64 rows x 8 float4-chunks = 512 chunks, 2 per thread
#pragma unroll
        for (int i = 0; i < 2; i++) {
            int c  = tid + i * 256;
            int m  = c >> 3;
            int kq = c & 7;
            int gr = bm + m; if (gr >= N) gr = N - 1;
            cp16(smem_u32(&As[s][m * G1_ASTR + kq * 4]),
                 x + (size_t)gr * F_IN + k0 + kq * 4);
        }
        // B: 16 kp-rows x 32 float4-chunks = 512 chunks, 2 per thread
#pragma unroll
        for (int i = 0; i < 2; i++) {
            int c  = tid + i * 256;
            int kp = c >> 5;
            int nq = c & 31;
            cp16(smem_u32(&Bs[s][kp * (2 * HID) + nq * 4]),
                 g_W1p + (size_t)(t * (G1_BK / 2) + kp) * (2 * HID) + nq * 4);
        }
    };

    stage(0, 0);
    asm volatile("cp.async.commit_group;" ::: "memory");

    for (int t = 0; t < G1_NT; t++) {
        asm volatile("cp.async.wait_group 0;" ::: "memory");
        __syncthreads();
        if (t + 1 < G1_NT) {
            stage(t + 1, (t + 1) & 1);
            asm volatile("cp.async.commit_group;" ::: "memory");
        }

        const float* pA = As[t & 1];
        const float* pB = Bs[t & 1];
#pragma unroll
        for (int kc = 0; kc < G1_BK / 4; kc++) {   // 4 k = 2 k-pairs per step
            float4 a4[4];
#pragma unroll
            for (int i = 0; i < 4; i++)
                a4[i] = *(const float4*)&pA[(m0 + i) * G1_ASTR + kc * 4];
            // kp0 = kc*2 (k even/odd pair 0), kp1 = kc*2+1
#pragma unroll
            for (int h = 0; h < 2; h++) {
                int kp = kc * 2 + h;
                float4 b0 = *(const float4*)&pB[kp * (2 * HID) + n0 * 2];
                float4 b1 = *(const float4*)&pB[kp * (2 * HID) + n0 * 2 + 4];
                ull bu0 = *(const ull*)&b0.x;   // n0   (even,odd)
                ull bu1 = *(const ull*)&b0.z;   // n0+1
                ull bu2 = *(const ull*)&b1.x;   // n0+2
                ull bu3 = *(const ull*)&b1.z;   // n0+3
#pragma unroll
                for (int i = 0; i < 4; i++) {
                    ull av = (h == 0) ? *(const ull*)&a4[i].x
                                      : *(const ull*)&a4[i].z;
                    acc[i][0] = fma2(av, bu0, acc[i][0]);
                    acc[i][1] = fma2(av, bu1, acc[i][1]);
                    acc[i][2] = fma2(av, bu2, acc[i][2]);
                    acc[i][3] = fma2(av, bu3, acc[i][3]);
                }
            }
        }
        __syncthreads();
    }

#pragma unroll
    for (int i = 0; i < 4; i++) {
        int r = bm + m0 + i;
        if (r < N) {
            float4 o;
            float lo, hi;
            unpack2(acc[i][0], lo, hi); o.x = lo + hi;
            unpack2(acc[i][1], lo, hi); o.y = lo + hi;
            unpack2(acc[i][2], lo, hi); o.z = lo + hi;
            unpack2(acc[i][3], lo, hi); o.w = lo + hi;
            *(float4*)(g_h1 + (size_t)r * HID + n0) = o;
        }
    }
}

// ---------------- layer-1 aggregation (CSR, warp per node) --------------------
// 32 threads per node, float2 per lane; unroll-4 batched gathers (MLP=4).
// Fuses self-loop, bias, relu.
__global__ void __launch_bounds__(256) k_agg1(const float* __restrict__ b1, int N) {
    int node = blockIdx.x * 8 + (threadIdx.x >> 5);
    int t = threadIdx.x & 31;
    if (node >= N) return;
    int beg = g_off[node], end = g_off[node + 1];
    float di = g_deg[node];
    float s2 = di * di;
    const float2* h1p = (const float2*)g_h1;  // 32 float2 per row
    float2 h0 = h1p[(size_t)node * 32 + t];
    float2 acc; acc.x = h0.x * s2; acc.y = h0.y * s2;

    int p = beg;
    for (; p + 4 <= end; p += 4) {
        int2 e0 = __ldg(&g_edge[p]);
        int2 e1 = __ldg(&g_edge[p + 1]);
        int2 e2 = __ldg(&g_edge[p + 2]);
        int2 e3 = __ldg(&g_edge[p + 3]);
        float2 v0 = h1p[(size_t)e0.x * 32 + t];
        float2 v1 = h1p[(size_t)e1.x * 32 + t];
        float2 v2 = h1p[(size_t)e2.x * 32 + t];
        float2 v3 = h1p[(size_t)e3.x * 32 + t];
        float n0f = __int_as_float(e0.y), n1f = __int_as_float(e1.y);
        float n2f = __int_as_float(e2.y), n3f = __int_as_float(e3.y);
        acc.x = fmaf(n0f, v0.x, acc.x); acc.y = fmaf(n0f, v0.y, acc.y);
        acc.x = fmaf(n1f, v1.x, acc.x); acc.y = fmaf(n1f, v1.y, acc.y);
        acc.x = fmaf(n2f, v2.x, acc.x); acc.y = fmaf(n2f, v2.y, acc.y);
        acc.x = fmaf(n3f, v3.x, acc.x); acc.y = fmaf(n3f, v3.y, acc.y);
    }
    for (; p < end; p++) {
        int2 e = __ldg(&g_edge[p]);
        float2 v = h1p[(size_t)e.x * 32 + t];
        float nf = __int_as_float(e.y);
        acc.x = fmaf(nf, v.x, acc.x); acc.y = fmaf(nf, v.y, acc.y);
    }
    acc.x += __ldg(b1 + t * 2);
    acc.y += __ldg(b1 + t * 2 + 1);
    float2 o; o.x = fmaxf(acc.x, 0.f); o.y = fmaxf(acc.y, 0.f);
    ((float2*)g_r1)[(size_t)node * 32 + t] = o;
}

// ---------------- GEMM2: h2[N,16] = r1[N,64] @ W2[16,64]^T --------------------
__global__ void __launch_bounds__(256) k_gemm2(const float* __restrict__ W2, int N) {
    __shared__ float Ws[NCLS * HID];
    int tid = threadIdx.x;
    for (int i = tid; i < NCLS * HID; i += 256) Ws[i] = W2[i];
    __syncthreads();

    int i  = blockIdx.x * 64 + (tid >> 2);
    int co = (tid & 3) * 4;
    if (i >= N) return;

    float a0 = 0.f, a1 = 0.f, a2 = 0.f, a3 = 0.f;
    const float4* rowp = (const float4*)(g_r1 + (size_t)i * HID);
#pragma unroll
    for (int k4 = 0; k4 < 16; k4++) {
        float4 v  = rowp[k4];
        float4 w0 = *(const float4*)&Ws[(co + 0) * HID + k4 * 4];
        float4 w1 = *(const float4*)&Ws[(co + 1) * HID + k4 * 4];
        float4 w2 = *(const float4*)&Ws[(co + 2) * HID + k4 * 4];
        float4 w3 = *(const float4*)&Ws[(co + 3) * HID + k4 * 4];
        a0 += v.x * w0.x + v.y * w0.y + v.z * w0.z + v.w * w0.w;
        a1 += v.x * w1.x + v.y * w1.y + v.z * w1.z + v.w * w1.w;
        a2 += v.x * w2.x + v.y * w2.y + v.z * w2.z + v.w * w2.w;
        a3 += v.x * w3.x + v.y * w3.y + v.z * w3.z + v.w * w3.w;
    }
    *(float4*)(g_h2 + (size_t)i * NCLS + co) = make_float4(a0, a1, a2, a3);
}

// ---------------- layer-2 aggregation + bias + log_softmax --------------------
// 16 threads per node; unroll-4; shuffle reduction within 16-lane groups.
__global__ void __launch_bounds__(256) k_agg2(float* __restrict__ out,
                                              const float* __restrict__ b2, int N) {
    int node = blockIdx.x * 16 + (threadIdx.x >> 4);
    int t = threadIdx.x & 15;
    bool valid = (node < N);
    if (!valid) node = N - 1;

    int beg = g_off[node], end = g_off[node + 1];
    float di = g_deg[node];
    float acc = g_h2[(size_t)node * NCLS + t] * di * di;
    int p = beg;
    for (; p + 4 <= end; p += 4) {
        int2 e0 = __ldg(&g_edge[p]);
        int2 e1 = __ldg(&g_edge[p + 1]);
        int2 e2 = __ldg(&g_edge[p + 2]);
        int2 e3 = __ldg(&g_edge[p + 3]);
        float v0 = g_h2[(size_t)e0.x * NCLS + t];
        float v1 = g_h2[(size_t)e1.x * NCLS + t];
        float v2 = g_h2[(size_t)e2.x * NCLS + t];
        float v3 = g_h2[(size_t)e3.x * NCLS + t];
        acc = fmaf(__int_as_float(e0.y), v0, acc);
        acc = fmaf(__int_as_float(e1.y), v1, acc);
        acc = fmaf(__int_as_float(e2.y), v2, acc);
        acc = fmaf(__int_as_float(e3.y), v3, acc);
    }
    for (; p < end; p++) {
        int2 e = __ldg(&g_edge[p]);
        acc = fmaf(__int_as_float(e.y), g_h2[(size_t)e.x * NCLS + t], acc);
    }
    float v = acc + __ldg(b2 + t);

    unsigned mask = 0xFFFFFFFFu;
    float m = v;
#pragma unroll
    for (int off = 8; off; off >>= 1) m = fmaxf(m, __shfl_xor_sync(mask, m, off));
    float s = expf(v - m);
#pragma unroll
    for (int off = 8; off; off >>= 1) s += __shfl_xor_sync(mask, s, off);
    if (valid) out[(size_t)node * NCLS + t] = v - m - logf(s);
}

// ---------------- launch ------------------------------------------------------
extern "C" void kernel_launch(void* const* d_in, const int* in_sizes, int n_in,
                              void* d_out, int out_size) {
    const float* x  = (const float*)d_in[0];
    const int*   ei = (const int*)d_in[1];
    const float* ea = (const float*)d_in[2];
    const float* W1 = (const float*)d_in[3];
    const float* b1 = (const float*)d_in[4];
    const float* W2 = (const float*)d_in[5];
    const float* b2 = (const float*)d_in[6];
    float* out = (float*)d_out;

    int N = in_sizes[0] / F_IN;
    int E = in_sizes[2];
    const int* rowp = ei;       // edge_index[0] = source
    const int* colp = ei + E;   // edge_index[1] = target

    int tb = 256;
    // order chosen so k_gemm1 is the 4th launch (ncu -s 5 sampling window)
    k_init<<<(N + tb - 1) / tb, tb>>>(N);
    k_w1p<<<(HID * F_IN + tb - 1) / tb, tb>>>(W1);
    k_count<<<(E + tb - 1) / tb, tb>>>(colp, ea, E);
    k_gemm1<<<(N + 63) / 64, 256>>>(x, N);
    k_dinv<<<(N + tb - 1) / tb, tb>>>(N);
    k_scan<<<1, 1024>>>(N);
    k_scatter<<<(E + tb - 1) / tb, tb>>>(rowp, colp, ea, E);

    k_agg1<<<(N + 7) / 8, 256>>>(b1, N);
    k_gemm2<<<(N + 63) / 64, 256>>>(W2, N);
    k_agg2<<<(N + 15) / 16, 256>>>(out, b2, N);
}

// round 5
// speedup vs baseline: 1.6556x; 1.6556x over previous
#include <cuda_runtime.h>

#define F_IN 512
#define HID  64
#define NCLS 16
#define NMAX 100000
#define EMAX 3200000

typedef unsigned long long ull;

// ---------------- scratch (static device globals; no allocation) -------------
__device__ __align__(16) float g_h1[NMAX * HID];    // x @ W1^T
__device__ __align__(16) float g_r1[NMAX * HID];    // relu(agg1 + b1)
__device__ __align__(16) float g_h2[NMAX * NCLS];   // r1 @ W2^T
__device__ __align__(16) float g_W1t[F_IN * HID];   // W1 transposed [k][n]
__device__ float g_deg[NMAX];                       // deg -> dinv in place
__device__ int   g_off[NMAX + 1];                   // CSR offsets (by target)
__device__ int   g_cur[NMAX];                       // counts -> cursors
__device__ int   g_bsum[512];                       // per-block scan partials
__device__ int2  g_edge[EMAX];                      // packed (src, norm)

// ---------------- PTX helpers -------------------------------------------------
__device__ __forceinline__ unsigned smem_u32(const void* p) {
    unsigned r;
    asm("{ .reg .u64 u; cvta.to.shared.u64 u, %1; cvt.u32.u64 %0, u; }"
        : "=r"(r) : "l"(p));
    return r;
}
__device__ __forceinline__ void cp16(unsigned d, const void* s) {
    asm volatile("cp.async.cg.shared.global [%0], [%1], 16;" :: "r"(d), "l"(s));
}
__device__ __forceinline__ ull pack2(float lo, float hi) {
    ull r; asm("mov.b64 %0, {%1, %2};" : "=l"(r) : "f"(lo), "f"(hi)); return r;
}
__device__ __forceinline__ ull fma2(ull a, ull b, ull c) {
    ull d; asm("fma.rn.f32x2 %0, %1, %2, %3;" : "=l"(d) : "l"(a), "l"(b), "l"(c));
    return d;
}

// ---------------- prep: init counters/deg + W1 transpose ----------------------
__global__ void k_prep(const float* __restrict__ W1, int N) {
    int i = blockIdx.x * blockDim.x + threadIdx.x;
    if (i < N) { g_cur[i] = 0; g_deg[i] = 1.0f; }  // self-loop weight
    if (i < HID * F_IN) {
        int n = i >> 9, k = i & 511;
        g_W1t[k * HID + n] = W1[i];
    }
}

// ---------------- GEMM1 (+ fused edge count) ---------------------------------
// GEMM blocks: h1[N,64] = x[N,512] @ W1[64,512]^T.
// BM=128, BN=64, BK=32; 256 threads; 8(m) x 4(n) per thread, f32x2 along N.
// Blocks >= gemmBlocks: degree count + weighted degree accum (independent work,
// hidden under the fma-bound GEMM).
#define G1_BK   32
#define G1_NT   (F_IN / G1_BK)          // 16 tiles
#define G1_ASTR 36                       // A row stride in floats (32 + 4 pad)

__global__ void __launch_bounds__(256, 2) k_gemm1_count(
        const float* __restrict__ x, int N, int gemmBlocks,
        const int* __restrict__ col, const float* __restrict__ ew, int E) {
    if ((int)blockIdx.x >= gemmBlocks) {
        int i = (blockIdx.x - gemmBlocks) * 256 + threadIdx.x;
        if (i < E) {
            int c = col[i];
            atomicAdd(&g_cur[c], 1);
            atomicAdd(&g_deg[c], ew[i]);
        }
        return;
    }

    __shared__ float As[3][128 * G1_ASTR];  // [m][k] padded
    __shared__ float Bs[3][G1_BK * HID];    // [k][n]

    int tid = threadIdx.x;
    int tx = tid & 15;        // n0 = 4*tx
    int ty = tid >> 4;        // m0 = 8*ty
    int n0 = tx * 4;
    int m0 = ty * 8;
    int bm = blockIdx.x * 128;

    ull acc[8][2];
#pragma unroll
    for (int i = 0; i < 8; i++) { acc[i][0] = 0ull; acc[i][1] = 0ull; }

    auto stage = [&](int t, int s) {
        int k0 = t * G1_BK;
        // A: 128 rows x 8 float4-chunks = 1024 chunks, 4 per thread
#pragma unroll
        for (int i = 0; i < 4; i++) {
            int c  = tid + i * 256;
            int m  = c >> 3;
            int kq = c & 7;
            int gr = bm + m; if (gr >= N) gr = N - 1;
            cp16(smem_u32(&As[s][m * G1_ASTR + kq * 4]),
                 x + (size_t)gr * F_IN + k0 + kq * 4);
        }
        // B: 32 rows x 16 float4-chunks = 512 chunks, 2 per thread
#pragma unroll
        for (int i = 0; i < 2; i++) {
            int c  = tid + i * 256;
            int kr = c >> 4;
            int nq = c & 15;
            cp16(smem_u32(&Bs[s][kr * HID + nq * 4]),
                 g_W1t + (size_t)(k0 + kr) * HID + nq * 4);
        }
    };

    stage(0, 0);
    asm volatile("cp.async.commit_group;" ::: "memory");
    stage(1, 1);
    asm volatile("cp.async.commit_group;" ::: "memory");

    for (int t = 0; t < G1_NT; t++) {
        asm volatile("cp.async.wait_group 1;" ::: "memory");
        __syncthreads();
        if (t + 2 < G1_NT) stage(t + 2, (t + 2) % 3);
        asm volatile("cp.async.commit_group;" ::: "memory");

        const float* pA = As[t % 3];
        const float* pB = Bs[t % 3];
#pragma unroll
        for (int kc = 0; kc < G1_BK / 4; kc++) {
            float4 a4[8];
#pragma unroll
            for (int i = 0; i < 8; i++)
                a4[i] = *(const float4*)&pA[(m0 + i) * G1_ASTR + kc * 4];
#pragma unroll
            for (int kk = 0; kk < 4; kk++) {
                float4 bv = *(const float4*)&pB[(kc * 4 + kk) * HID + n0];
                ull w0 = pack2(bv.x, bv.y);
                ull w1 = pack2(bv.z, bv.w);
#pragma unroll
                for (int i = 0; i < 8; i++) {
                    float av = (&a4[i].x)[kk];
                    ull aa = pack2(av, av);
                    acc[i][0] = fma2(aa, w0, acc[i][0]);
                    acc[i][1] = fma2(aa, w1, acc[i][1]);
                }
            }
        }
    }

#pragma unroll
    for (int i = 0; i < 8; i++) {
        int r = bm + m0 + i;
        if (r < N) {
            float4 o;
            *(ull*)&o.x = acc[i][0];
            *(ull*)&o.z = acc[i][1];
            *(float4*)(g_h1 + (size_t)r * HID + n0) = o;
        }
    }
}

// ---------------- hierarchical scan (3 small kernels) + fused dinv ------------
// scan1: per-256-block local exclusive scan of g_cur -> g_off; block sums ->
// g_bsum. Also converts g_deg -> dinv (count is complete by now).
__global__ void __launch_bounds__(256) k_scan1(int N) {
    int gid = blockIdx.x * 256 + threadIdx.x;
    int tid = threadIdx.x;
    int v = (gid < N) ? g_cur[gid] : 0;

    if (gid < N) {
        float d = g_deg[gid];
        g_deg[gid] = (d > 0.0f) ? rsqrtf(d) : 0.0f;
    }

    int lane = tid & 31, w = tid >> 5;
    int s = v;
#pragma unroll
    for (int off = 1; off < 32; off <<= 1) {
        int u = __shfl_up_sync(0xFFFFFFFFu, s, off);
        if (lane >= off) s += u;
    }
    __shared__ int wsum[8], woff[8];
    if (lane == 31) wsum[w] = s;
    __syncthreads();
    if (tid < 8) {
        int p = 0;
#pragma unroll
        for (int j = 0; j < 8; j++) { if (j < tid) p += wsum[j]; }
        woff[tid] = p;
    }
    __syncthreads();
    int excl = s - v + woff[w];
    if (gid < N) g_off[gid] = excl;
    if (tid == 255) g_bsum[blockIdx.x] = excl + v;  // block total
}
// scan2: 1 block, exclusive-scan the NB block sums; writes g_off[N] = total.
__global__ void __launch_bounds__(512) k_scan2(int NB, int N) {
    __shared__ int sh[512];
    int t = threadIdx.x;
    int v = (t < NB) ? g_bsum[t] : 0;
    sh[t] = v;
    __syncthreads();
    for (int off = 1; off < 512; off <<= 1) {
        int u = (t >= off) ? sh[t - off] : 0;
        __syncthreads();
        sh[t] += u;
        __syncthreads();
    }
    if (t < NB) g_bsum[t] = sh[t] - v;           // exclusive
    if (t == NB - 1) g_off[N] = sh[t];           // total
}
// scan3: add block offsets; produce final offsets + cursors.
__global__ void __launch_bounds__(256) k_scan3(int N) {
    int gid = blockIdx.x * 256 + threadIdx.x;
    if (gid < N) {
        int o = g_off[gid] + g_bsum[gid >> 8];
        g_off[gid] = o;
        g_cur[gid] = o;
    }
}

__global__ void k_scatter(const int* __restrict__ row, const int* __restrict__ col,
                          const float* __restrict__ ew, int E) {
    int i = blockIdx.x * blockDim.x + threadIdx.x;
    if (i >= E) return;
    int r = row[i], c = col[i];
    float nrm = g_deg[r] * ew[i] * g_deg[c];  // g_deg holds dinv here
    int p = atomicAdd(&g_cur[c], 1);
    int2 v; v.x = r; v.y = __float_as_int(nrm);
    g_edge[p] = v;
}

// ---------------- layer-1 aggregation (CSR, warp per node) --------------------
// 32 threads per node, float2 per lane; unroll-8 batched gathers (MLP=8).
// Fuses self-loop, bias, relu.
__global__ void __launch_bounds__(256) k_agg1(const float* __restrict__ b1, int N) {
    int node = blockIdx.x * 8 + (threadIdx.x >> 5);
    int t = threadIdx.x & 31;
    if (node >= N) return;
    int beg = g_off[node], end = g_off[node + 1];
    float di = g_deg[node];
    float s2 = di * di;
    const float2* h1p = (const float2*)g_h1;  // 32 float2 per row
    float2 h0 = h1p[(size_t)node * 32 + t];
    float2 acc; acc.x = h0.x * s2; acc.y = h0.y * s2;

    int p = beg;
    for (; p + 8 <= end; p += 8) {
        int2 e[8];
#pragma unroll
        for (int j = 0; j < 8; j++) e[j] = __ldg(&g_edge[p + j]);
        float2 v[8];
#pragma unroll
        for (int j = 0; j < 8; j++) v[j] = h1p[(size_t)e[j].x * 32 + t];
#pragma unroll
        for (int j = 0; j < 8; j++) {
            float nf = __int_as_float(e[j].y);
            acc.x = fmaf(nf, v[j].x, acc.x);
            acc.y = fmaf(nf, v[j].y, acc.y);
        }
    }
    for (; p < end; p++) {
        int2 e = __ldg(&g_edge[p]);
        float2 v = h1p[(size_t)e.x * 32 + t];
        float nf = __int_as_float(e.y);
        acc.x = fmaf(nf, v.x, acc.x); acc.y = fmaf(nf, v.y, acc.y);
    }
    acc.x += __ldg(b1 + t * 2);
    acc.y += __ldg(b1 + t * 2 + 1);
    float2 o; o.x = fmaxf(acc.x, 0.f); o.y = fmaxf(acc.y, 0.f);
    ((float2*)g_r1)[(size_t)node * 32 + t] = o;
}

// ---------------- GEMM2: h2[N,16] = r1[N,64] @ W2[16,64]^T --------------------
__global__ void __launch_bounds__(256) k_gemm2(const float* __restrict__ W2, int N) {
    __shared__ float Ws[NCLS * HID];
    int tid = threadIdx.x;
    for (int i = tid; i < NCLS * HID; i += 256) Ws[i] = W2[i];
    __syncthreads();

    int i  = blockIdx.x * 64 + (tid >> 2);
    int co = (tid & 3) * 4;
    if (i >= N) return;

    float a0 = 0.f, a1 = 0.f, a2 = 0.f, a3 = 0.f;
    const float4* rowp = (const float4*)(g_r1 + (size_t)i * HID);
#pragma unroll
    for (int k4 = 0; k4 < 16; k4++) {
        float4 v  = rowp[k4];
        float4 w0 = *(const float4*)&Ws[(co + 0) * HID + k4 * 4];
        float4 w1 = *(const float4*)&Ws[(co + 1) * HID + k4 * 4];
        float4 w2 = *(const float4*)&Ws[(co + 2) * HID + k4 * 4];
        float4 w3 = *(const float4*)&Ws[(co + 3) * HID + k4 * 4];
        a0 += v.x * w0.x + v.y * w0.y + v.z * w0.z + v.w * w0.w;
        a1 += v.x * w1.x + v.y * w1.y + v.z * w1.z + v.w * w1.w;
        a2 += v.x * w2.x + v.y * w2.y + v.z * w2.z + v.w * w2.w;
        a3 += v.x * w3.x + v.y * w3.y + v.z * w3.z + v.w * w3.w;
    }
    *(float4*)(g_h2 + (size_t)i * NCLS + co) = make_float4(a0, a1, a2, a3);
}

// ---------------- layer-2 aggregation + bias + log_softmax --------------------
// 16 threads per node; unroll-8; shuffle reduction within 16-lane groups.
__global__ void __launch_bounds__(256) k_agg2(float* __restrict__ out,
                                              const float* __restrict__ b2, int N) {
    int node = blockIdx.x * 16 + (threadIdx.x >> 4);
    int t = threadIdx.x & 15;
    bool valid = (node < N);
    if (!valid) node = N - 1;

    int beg = g_off[node], end = g_off[node + 1];
    float di = g_deg[node];
    float acc = g_h2[(size_t)node * NCLS + t] * di * di;
    int p = beg;
    for (; p + 8 <= end; p += 8) {
        int2 e[8];
#pragma unroll
        for (int j = 0; j < 8; j++) e[j] = __ldg(&g_edge[p + j]);
        float v[8];
#pragma unroll
        for (int j = 0; j < 8; j++) v[j] = g_h2[(size_t)e[j].x * NCLS + t];
#pragma unroll
        for (int j = 0; j < 8; j++)
            acc = fmaf(__int_as_float(e[j].y), v[j], acc);
    }
    for (; p < end; p++) {
        int2 e = __ldg(&g_edge[p]);
        acc = fmaf(__int_as_float(e.y), g_h2[(size_t)e.x * NCLS + t], acc);
    }
    float v = acc + __ldg(b2 + t);

    unsigned mask = 0xFFFFFFFFu;
    float m = v;
#pragma unroll
    for (int off = 8; off; off >>= 1) m = fmaxf(m, __shfl_xor_sync(mask, m, off));
    float s = expf(v - m);
#pragma unroll
    for (int off = 8; off; off >>= 1) s += __shfl_xor_sync(mask, s, off);
    if (valid) out[(size_t)node * NCLS + t] = v - m - logf(s);
}

// ---------------- launch ------------------------------------------------------
extern "C" void kernel_launch(void* const* d_in, const int* in_sizes, int n_in,
                              void* d_out, int out_size) {
    const float* x  = (const float*)d_in[0];
    const int*   ei = (const int*)d_in[1];
    const float* ea = (const float*)d_in[2];
    const float* W1 = (const float*)d_in[3];
    const float* b1 = (const float*)d_in[4];
    const float* W2 = (const float*)d_in[5];
    const float* b2 = (const float*)d_in[6];
    float* out = (float*)d_out;

    int N = in_sizes[0] / F_IN;
    int E = in_sizes[2];
    const int* rowp = ei;       // edge_index[0] = source
    const int* colp = ei + E;   // edge_index[1] = target

    int tb = 256;
    int nBlk = (N + tb - 1) / tb;                 // 391
    int prepBlk = ((HID * F_IN > N ? HID * F_IN : N) + tb - 1) / tb;
    int gemmBlocks  = (N + 127) / 128;
    int countBlocks = (E + tb - 1) / tb;

    k_prep<<<prepBlk, tb>>>(W1, N);
    k_gemm1_count<<<gemmBlocks + countBlocks, 256>>>(x, N, gemmBlocks, colp, ea, E);
    k_scan1<<<nBlk, tb>>>(N);
    k_scan2<<<1, 512>>>(nBlk, N);
    k_scan3<<<nBlk, tb>>>(N);
    k_scatter<<<countBlocks, tb>>>(rowp, colp, ea, E);

    k_agg1<<<(N + 7) / 8, 256>>>(b1, N);
    k_gemm2<<<(N + 63) / 64, 256>>>(W2, N);
    k_agg2<<<(N + 15) / 16, 256>>>(out, b2, N);
}

// round 7
// speedup vs baseline: 1.6827x; 1.0164x over previous
#include <cuda_runtime.h>
#include <cuda_fp16.h>

#define F_IN 512
#define HID  64
#define NCLS 16
#define NMAX 100000
#define EMAX 3200000

typedef unsigned long long ull;

// ---------------- scratch (static device globals; no allocation) -------------
__device__ __align__(16) __half g_h1[NMAX * HID];   // x @ W1^T (fp16 staging)
__device__ __align__(16) float g_r1[NMAX * HID];    // relu(agg1 + b1)
__device__ __align__(16) float g_h2[NMAX * NCLS];   // r1 @ W2^T
__device__ __align__(16) float g_W1t[F_IN * HID];   // W1 transposed [k][n]
__device__ float g_deg[NMAX];                       // deg -> dinv in place
__device__ int   g_off[NMAX + 1];                   // CSR offsets (by target)
__device__ int   g_cur[NMAX];                       // counts -> cursors
__device__ int   g_bsum[512];                       // per-block scan partials
__device__ int2  g_edge[EMAX];                      // packed (src, norm)

// ---------------- PTX helpers -------------------------------------------------
__device__ __forceinline__ unsigned smem_u32(const void* p) {
    unsigned r;
    asm("{ .reg .u64 u; cvta.to.shared.u64 u, %1; cvt.u32.u64 %0, u; }"
        : "=r"(r) : "l"(p));
    return r;
}
__device__ __forceinline__ void cp16(unsigned d, const void* s) {
    asm volatile("cp.async.cg.shared.global [%0], [%1], 16;" :: "r"(d), "l"(s));
}
__device__ __forceinline__ ull pack2(float lo, float hi) {
    ull r; asm("mov.b64 %0, {%1, %2};" : "=l"(r) : "f"(lo), "f"(hi)); return r;
}
__device__ __forceinline__ ull fma2(ull a, ull b, ull c) {
    ull d; asm("fma.rn.f32x2 %0, %1, %2, %3;" : "=l"(d) : "l"(a), "l"(b), "l"(c));
    return d;
}
__device__ __forceinline__ void unpack2(ull v, float& lo, float& hi) {
    asm("mov.b64 {%0, %1}, %2;" : "=f"(lo), "=f"(hi) : "l"(v));
}

// ---------------- prep: init counters/deg + W1 transpose ----------------------
__global__ void k_prep(const float* __restrict__ W1, int N) {
    int i = blockIdx.x * blockDim.x + threadIdx.x;
    if (i < N) { g_cur[i] = 0; g_deg[i] = 1.0f; }  // self-loop weight
    if (i < HID * F_IN) {
        int n = i >> 9, k = i & 511;
        g_W1t[k * HID + n] = W1[i];
    }
}

// ---------------- GEMM1 (+ fused edge count) ---------------------------------
// GEMM blocks: h1[N,64] = x[N,512] @ W1[64,512]^T -> fp16 staging.
// BM=128, BN=64, BK=32; 256 threads; 8(m) x 4(n) per thread, f32x2 along N.
// Blocks >= gemmBlocks: degree count + weighted degree accum (independent work,
// hidden under the fma-bound GEMM).
#define G1_BK   32
#define G1_NT   (F_IN / G1_BK)          // 16 tiles
#define G1_ASTR 36                       // A row stride in floats (32 + 4 pad)

__global__ void __launch_bounds__(256, 2) k_gemm1_count(
        const float* __restrict__ x, int N, int gemmBlocks,
        const int* __restrict__ col, const float* __restrict__ ew, int E) {
    if ((int)blockIdx.x >= gemmBlocks) {
        int i = (blockIdx.x - gemmBlocks) * 256 + threadIdx.x;
        if (i < E) {
            int c = col[i];
            atomicAdd(&g_cur[c], 1);
            atomicAdd(&g_deg[c], ew[i]);
        }
        return;
    }

    __shared__ float As[3][128 * G1_ASTR];  // [m][k] padded
    __shared__ float Bs[3][G1_BK * HID];    // [k][n]

    int tid = threadIdx.x;
    int tx = tid & 15;        // n0 = 4*tx
    int ty = tid >> 4;        // m0 = 8*ty
    int n0 = tx * 4;
    int m0 = ty * 8;
    int bm = blockIdx.x * 128;

    ull acc[8][2];
#pragma unroll
    for (int i = 0; i < 8; i++) { acc[i][0] = 0ull; acc[i][1] = 0ull; }

    auto stage = [&](int t, int s) {
        int k0 = t * G1_BK;
        // A: 128 rows x 8 float4-chunks = 1024 chunks, 4 per thread
#pragma unroll
        for (int i = 0; i < 4; i++) {
            int c  = tid + i * 256;
            int m  = c >> 3;
            int kq = c & 7;
            int gr = bm + m; if (gr >= N) gr = N - 1;
            cp16(smem_u32(&As[s][m * G1_ASTR + kq * 4]),
                 x + (size_t)gr * F_IN + k0 + kq * 4);
        }
        // B: 32 rows x 16 float4-chunks = 512 chunks, 2 per thread
#pragma unroll
        for (int i = 0; i < 2; i++) {
            int c  = tid + i * 256;
            int kr = c >> 4;
            int nq = c & 15;
            cp16(smem_u32(&Bs[s][kr * HID + nq * 4]),
                 g_W1t + (size_t)(k0 + kr) * HID + nq * 4);
        }
    };

    stage(0, 0);
    asm volatile("cp.async.commit_group;" ::: "memory");
    stage(1, 1);
    asm volatile("cp.async.commit_group;" ::: "memory");

    for (int t = 0; t < G1_NT; t++) {
        asm volatile("cp.async.wait_group 1;" ::: "memory");
        __syncthreads();
        if (t + 2 < G1_NT) stage(t + 2, (t + 2) % 3);
        asm volatile("cp.async.commit_group;" ::: "memory");

        const float* pA = As[t % 3];
        const float* pB = Bs[t % 3];
#pragma unroll
        for (int kc = 0; kc < G1_BK / 4; kc++) {
            float4 a4[8];
#pragma unroll
            for (int i = 0; i < 8; i++)
                a4[i] = *(const float4*)&pA[(m0 + i) * G1_ASTR + kc * 4];
#pragma unroll
            for (int kk = 0; kk < 4; kk++) {
                float4 bv = *(const float4*)&pB[(kc * 4 + kk) * HID + n0];
                ull w0 = pack2(bv.x, bv.y);
                ull w1 = pack2(bv.z, bv.w);
#pragma unroll
                for (int i = 0; i < 8; i++) {
                    float av = (&a4[i].x)[kk];
                    ull aa = pack2(av, av);
                    acc[i][0] = fma2(aa, w0, acc[i][0]);
                    acc[i][1] = fma2(aa, w1, acc[i][1]);
                }
            }
        }
    }

#pragma unroll
    for (int i = 0; i < 8; i++) {
        int r = bm + m0 + i;
        if (r < N) {
            float l0, h0v, l1, h1v;
            unpack2(acc[i][0], l0, h0v);   // (n0, n0+1)
            unpack2(acc[i][1], l1, h1v);   // (n0+2, n0+3)
            __half2 p0 = __floats2half2_rn(l0, h0v);
            __half2 p1 = __floats2half2_rn(l1, h1v);
            uint2 o;
            o.x = *(unsigned*)&p0;
            o.y = *(unsigned*)&p1;
            *(uint2*)(g_h1 + (size_t)r * HID + n0) = o;
        }
    }
}

// ---------------- hierarchical scan (3 small kernels) + fused dinv ------------
__global__ void __launch_bounds__(256) k_scan1(int N) {
    int gid = blockIdx.x * 256 + threadIdx.x;
    int tid = threadIdx.x;
    int v = (gid < N) ? g_cur[gid] : 0;

    if (gid < N) {
        float d = g_deg[gid];
        g_deg[gid] = (d > 0.0f) ? rsqrtf(d) : 0.0f;
    }

    int lane = tid & 31, w = tid >> 5;
    int s = v;
#pragma unroll
    for (int off = 1; off < 32; off <<= 1) {
        int u = __shfl_up_sync(0xFFFFFFFFu, s, off);
        if (lane >= off) s += u;
    }
    __shared__ int wsum[8], woff[8];
    if (lane == 31) wsum[w] = s;
    __syncthreads();
    if (tid < 8) {
        int p = 0;
#pragma unroll
        for (int j = 0; j < 8; j++) { if (j < tid) p += wsum[j]; }
        woff[tid] = p;
    }
    __syncthreads();
    int excl = s - v + woff[w];
    if (gid < N) g_off[gid] = excl;
    if (tid == 255) g_bsum[blockIdx.x] = excl + v;  // block total
}
__global__ void __launch_bounds__(512) k_scan2(int NB, int N) {
    __shared__ int sh[512];
    int t = threadIdx.x;
    int v = (t < NB) ? g_bsum[t] : 0;
    sh[t] = v;
    __syncthreads();
    for (int off = 1; off < 512; off <<= 1) {
        int u = (t >= off) ? sh[t - off] : 0;
        __syncthreads();
        sh[t] += u;
        __syncthreads();
    }
    if (t < NB) g_bsum[t] = sh[t] - v;           // exclusive
    if (t == NB - 1) g_off[N] = sh[t];           // total
}
__global__ void __launch_bounds__(256) k_scan3(int N) {
    int gid = blockIdx.x * 256 + threadIdx.x;
    if (gid < N) {
        int o = g_off[gid] + g_bsum[gid >> 8];
        g_off[gid] = o;
        g_cur[gid] = o;
    }
}

__global__ void k_scatter(const int* __restrict__ row, const int* __restrict__ col,
                          const float* __restrict__ ew, int E) {
    int i = blockIdx.x * blockDim.x + threadIdx.x;
    if (i >= E) return;
    int r = row[i], c = col[i];
    float nrm = g_deg[r] * ew[i] * g_deg[c];  // g_deg holds dinv here
    int p = atomicAdd(&g_cur[c], 1);
    int2 v; v.x = r; v.y = __float_as_int(nrm);
    g_edge[p] = v;
}

// ---------------- layer-1 aggregation (CSR, warp per node) --------------------
// 32 threads per node, half2 per lane (full 128B row = 1 sector); unroll-8.
// fp32 accumulation; fuses self-loop, bias, relu.
__global__ void __launch_bounds__(256) k_agg1(const float* __restrict__ b1, int N) {
    int node = blockIdx.x * 8 + (threadIdx.x >> 5);
    int t = threadIdx.x & 31;
    if (node >= N) return;
    int beg = g_off[node], end = g_off[node + 1];
    float di = g_deg[node];
    float s2 = di * di;
    const __half2* h1p = (const __half2*)g_h1;  // 32 half2 per row
    float2 h0 = __half22float2(h1p[(size_t)node * 32 + t]);
    float2 acc; acc.x = h0.x * s2; acc.y = h0.y * s2;

    int p = beg;
    for (; p + 8 <= end; p += 8) {
        int2 e[8];
#pragma unroll
        for (int j = 0; j < 8; j++) e[j] = __ldg(&g_edge[p + j]);
        __half2 v[8];
#pragma unroll
        for (int j = 0; j < 8; j++) v[j] = h1p[(size_t)e[j].x * 32 + t];
#pragma unroll
        for (int j = 0; j < 8; j++) {
            float nf = __int_as_float(e[j].y);
            float2 f = __half22float2(v[j]);
            acc.x = fmaf(nf, f.x, acc.x);
            acc.y = fmaf(nf, f.y, acc.y);
        }
    }
    for (; p < end; p++) {
        int2 e = __ldg(&g_edge[p]);
        float2 f = __half22float2(h1p[(size_t)e.x * 32 + t]);
        float nf = __int_as_float(e.y);
        acc.x = fmaf(nf, f.x, acc.x); acc.y = fmaf(nf, f.y, acc.y);
    }
    acc.x += __ldg(b1 + t * 2);
    acc.y += __ldg(b1 + t * 2 + 1);
    float2 o; o.x = fmaxf(acc.x, 0.f); o.y = fmaxf(acc.y, 0.f);
    ((float2*)g_r1)[(size_t)node * 32 + t] = o;
}

// ---------------- GEMM2: h2[N,16] = r1[N,64] @ W2[16,64]^T --------------------
__global__ void __launch_bounds__(256) k_gemm2(const float* __restrict__ W2, int N) {
    __shared__ float Ws[NCLS * HID];
    int tid = threadIdx.x;
    for (int i = tid; i < NCLS * HID; i += 256) Ws[i] = W2[i];
    __syncthreads();

    int i  = blockIdx.x * 64 + (tid >> 2);
    int co = (tid & 3) * 4;
    if (i >= N) return;

    float a0 = 0.f, a1 = 0.f, a2 = 0.f, a3 = 0.f;
    const float4* rowp = (const float4*)(g_r1 + (size_t)i * HID);
#pragma unroll
    for (int k4 = 0; k4 < 16; k4++) {
        float4 v  = rowp[k4];
        float4 w0 = *(const float4*)&Ws[(co + 0) * HID + k4 * 4];
        float4 w1 = *(const float4*)&Ws[(co + 1) * HID + k4 * 4];
        float4 w2 = *(const float4*)&Ws[(co + 2) * HID + k4 * 4];
        float4 w3 = *(const float4*)&Ws[(co + 3) * HID + k4 * 4];
        a0 += v.x * w0.x + v.y * w0.y + v.z * w0.z + v.w * w0.w;
        a1 += v.x * w1.x + v.y * w1.y + v.z * w1.z + v.w * w1.w;
        a2 += v.x * w2.x + v.y * w2.y + v.z * w2.z + v.w * w2.w;
        a3 += v.x * w3.x + v.y * w3.y + v.z * w3.z + v.w * w3.w;
    }
    *(float4*)(g_h2 + (size_t)i * NCLS + co) = make_float4(a0, a1, a2, a3);
}

// ---------------- layer-2 aggregation + bias + log_softmax --------------------
__global__ void __launch_bounds__(256) k_agg2(float* __restrict__ out,
                                              const float* __restrict__ b2, int N) {
    int node = blockIdx.x * 16 + (threadIdx.x >> 4);
    int t = threadIdx.x & 15;
    bool valid = (node < N);
    if (!valid) node = N - 1;

    int beg = g_off[node], end = g_off[node + 1];
    float di = g_deg[node];
    float acc = g_h2[(size_t)node * NCLS + t] * di * di;
    int p = beg;
    for (; p + 8 <= end; p += 8) {
        int2 e[8];
#pragma unroll
        for (int j = 0; j < 8; j++) e[j] = __ldg(&g_edge[p + j]);
        float v[8];
#pragma unroll
        for (int j = 0; j < 8; j++) v[j] = g_h2[(size_t)e[j].x * NCLS + t];
#pragma unroll
        for (int j = 0; j < 8; j++)
            acc = fmaf(__int_as_float(e[j].y), v[j], acc);
    }
    for (; p < end; p++) {
        int2 e = __ldg(&g_edge[p]);
        acc = fmaf(__int_as_float(e.y), g_h2[(size_t)e.x * NCLS + t], acc);
    }
    float v = acc + __ldg(b2 + t);

    unsigned mask = 0xFFFFFFFFu;
    float m = v;
#pragma unroll
    for (int off = 8; off; off >>= 1) m = fmaxf(m, __shfl_xor_sync(mask, m, off));
    float s = expf(v - m);
#pragma unroll
    for (int off = 8; off; off >>= 1) s += __shfl_xor_sync(mask, s, off);
    if (valid) out[(size_t)node * NCLS + t] = v - m - logf(s);
}

// ---------------- launch ------------------------------------------------------
extern "C" void kernel_launch(void* const* d_in, const int* in_sizes, int n_in,
                              void* d_out, int out_size) {
    const float* x  = (const float*)d_in[0];
    const int*   ei = (const int*)d_in[1];
    const float* ea = (const float*)d_in[2];
    const float* W1 = (const float*)d_in[3];
    const float* b1 = (const float*)d_in[4];
    const float* W2 = (const float*)d_in[5];
    const float* b2 = (const float*)d_in[6];
    float* out = (float*)d_out;

    int N = in_sizes[0] / F_IN;
    int E = in_sizes[2];
    const int* rowp = ei;       // edge_index[0] = source
    const int* colp = ei + E;   // edge_index[1] = target

    int tb = 256;
    int nBlk = (N + tb - 1) / tb;                 // 391
    int prepBlk = ((HID * F_IN > N ? HID * F_IN : N) + tb - 1) / tb;
    int gemmBlocks  = (N + 127) / 128;
    int countBlocks = (E + tb - 1) / tb;

    k_prep<<<prepBlk, tb>>>(W1, N);
    k_gemm1_count<<<gemmBlocks + countBlocks, 256>>>(x, N, gemmBlocks, colp, ea, E);
    k_scan1<<<nBlk, tb>>>(N);
    k_scan2<<<1, 512>>>(nBlk, N);
    k_scan3<<<nBlk, tb>>>(N);
    k_scatter<<<countBlocks, tb>>>(rowp, colp, ea, E);

    k_agg1<<<(N + 7) / 8, 256>>>(b1, N);
    k_gemm2<<<(N + 63) / 64, 256>>>(W2, N);
    k_agg2<<<(N + 15) / 16, 256>>>(out, b2, N);
}